// round 3
// baseline (speedup 1.0000x reference)
#include <cuda_runtime.h>
#include <cstdint>

// Tropical (max-times) matvec: out[b, i] = max_j M[i, j] * x[b, j]
// B = 256, n = 2048. Single kernel, full-K per block, packed f32x2 multiplies.
// Grid 16 (i) x 8 (b) = 128 blocks. Tile: BM=128 x BN=32, BK=32.
// Thread tile: TM=8 (i) x TN=2 (b), 256 threads.

#define NN    2048
#define NB    256
#define BM    128
#define BN    32
#define BK    32
#define NITER (NN / BK)   // 64
#define THREADS 256

__device__ __forceinline__ unsigned long long dup_f32(float v) {
    unsigned long long r;
    unsigned int u = __float_as_uint(v);
    asm("mov.b64 %0, {%1, %1};" : "=l"(r) : "r"(u));
    return r;
}

__device__ __forceinline__ unsigned long long mul_f32x2(unsigned long long a,
                                                        unsigned long long b) {
    unsigned long long r;
    asm("mul.rn.f32x2 %0, %1, %2;" : "=l"(r) : "l"(a), "l"(b));
    return r;
}

__device__ __forceinline__ void unpack2(unsigned long long p, float& lo, float& hi) {
    unsigned int l, h;
    asm("mov.b64 {%0, %1}, %2;" : "=r"(l), "=r"(h) : "l"(p));
    lo = __uint_as_float(l);
    hi = __uint_as_float(h);
}

__global__ __launch_bounds__(THREADS, 1)
void trop_mm_kernel(const float* __restrict__ x, const float* __restrict__ M,
                    float* __restrict__ out)
{
    __shared__ float Ms[2][BK][BM + 4];   // [buf][j][i]  (132 floats/row, 16B-aligned rows)
    __shared__ float Xs[2][BK][BN + 2];   // [buf][j][b]

    const int tid = threadIdx.x;
    const int tx  = tid & 15;    // b-direction (16 groups of TN=2)
    const int ty  = tid >> 4;    // i-direction (16 groups of TM=8)
    const int i0  = blockIdx.x * BM;
    const int b0  = blockIdx.y * BN;

    // ---- loader coordinates ----
    const int m_row = tid >> 3;          // 0..31 (rows m_row + 32k, k=0..3)
    const int m_j4  = (tid & 7) * 4;     // 0..28
    const int x_b   = tid >> 3;          // 0..31
    const int x_j4  = (tid & 7) * 4;

    const float* Mg = M + (size_t)(i0 + m_row) * NN + m_j4;
    const float* Xg = x + (size_t)(b0 + x_b) * NN + x_j4;

    float4 mreg[4];
    float4 xreg;

    // ---- prologue: load + store stage 0 ----
    #pragma unroll
    for (int k = 0; k < 4; k++)
        mreg[k] = *(const float4*)(Mg + (size_t)(32 * k) * NN);
    xreg = *(const float4*)(Xg);

    #pragma unroll
    for (int k = 0; k < 4; k++) {
        Ms[0][m_j4 + 0][m_row + 32 * k] = mreg[k].x;
        Ms[0][m_j4 + 1][m_row + 32 * k] = mreg[k].y;
        Ms[0][m_j4 + 2][m_row + 32 * k] = mreg[k].z;
        Ms[0][m_j4 + 3][m_row + 32 * k] = mreg[k].w;
    }
    Xs[0][x_j4 + 0][x_b] = xreg.x;
    Xs[0][x_j4 + 1][x_b] = xreg.y;
    Xs[0][x_j4 + 2][x_b] = xreg.z;
    Xs[0][x_j4 + 3][x_b] = xreg.w;
    __syncthreads();

    const float NEG_INF = __int_as_float(0xff800000);
    float acc[8][2];
    #pragma unroll
    for (int a = 0; a < 8; a++) {
        acc[a][0] = NEG_INF;
        acc[a][1] = NEG_INF;
    }

    for (int kt = 0; kt < NITER; kt++) {
        const int buf = kt & 1;

        // prefetch next stage into registers (latency hidden under compute)
        if (kt + 1 < NITER) {
            const float* Mg2 = Mg + (kt + 1) * BK;
            #pragma unroll
            for (int k = 0; k < 4; k++)
                mreg[k] = *(const float4*)(Mg2 + (size_t)(32 * k) * NN);
            xreg = *(const float4*)(Xg + (kt + 1) * BK);
        }

        #pragma unroll
        for (int kk = 0; kk < BK; kk++) {
            const float* msrc = &Ms[buf][kk][ty * 8];
            ulonglong2 mA = *(const ulonglong2*)(msrc);       // (m0,m1),(m2,m3)
            ulonglong2 mB = *(const ulonglong2*)(msrc + 4);   // (m4,m5),(m6,m7)
            float2 xv = *(const float2*)&Xs[buf][kk][tx * 2];

            unsigned long long xx0 = dup_f32(xv.x);
            unsigned long long xx1 = dup_f32(xv.y);
            unsigned long long mp[4] = {mA.x, mA.y, mB.x, mB.y};

            #pragma unroll
            for (int q = 0; q < 4; q++) {
                float lo, hi;
                unpack2(mul_f32x2(mp[q], xx0), lo, hi);
                acc[2 * q + 0][0] = fmaxf(acc[2 * q + 0][0], lo);
                acc[2 * q + 1][0] = fmaxf(acc[2 * q + 1][0], hi);
                unpack2(mul_f32x2(mp[q], xx1), lo, hi);
                acc[2 * q + 0][1] = fmaxf(acc[2 * q + 0][1], lo);
                acc[2 * q + 1][1] = fmaxf(acc[2 * q + 1][1], hi);
            }
        }

        // stage next tile into the other buffer
        if (kt + 1 < NITER) {
            const int nb = buf ^ 1;
            #pragma unroll
            for (int k = 0; k < 4; k++) {
                Ms[nb][m_j4 + 0][m_row + 32 * k] = mreg[k].x;
                Ms[nb][m_j4 + 1][m_row + 32 * k] = mreg[k].y;
                Ms[nb][m_j4 + 2][m_row + 32 * k] = mreg[k].z;
                Ms[nb][m_j4 + 3][m_row + 32 * k] = mreg[k].w;
            }
            Xs[nb][x_j4 + 0][x_b] = xreg.x;
            Xs[nb][x_j4 + 1][x_b] = xreg.y;
            Xs[nb][x_j4 + 2][x_b] = xreg.z;
            Xs[nb][x_j4 + 3][x_b] = xreg.w;
        }
        __syncthreads();
    }

    // ---- epilogue: direct write to out[b][i] ----
    #pragma unroll
    for (int c = 0; c < 2; c++) {
        const int b = b0 + tx * 2 + c;
        float* row = out + (size_t)b * NN + i0 + ty * 8;
        *(float4*)(row)     = make_float4(acc[0][c], acc[1][c], acc[2][c], acc[3][c]);
        *(float4*)(row + 4) = make_float4(acc[4][c], acc[5][c], acc[6][c], acc[7][c]);
    }
}

extern "C" void kernel_launch(void* const* d_in, const int* in_sizes, int n_in,
                              void* d_out, int out_size)
{
    // x: [256, 2048] (524288), M: [2048, 2048] (4194304) — detect order defensively
    const float* x;
    const float* M;
    if (in_sizes[0] == NB * NN) { x = (const float*)d_in[0]; M = (const float*)d_in[1]; }
    else                        { x = (const float*)d_in[1]; M = (const float*)d_in[0]; }

    dim3 grid(NN / BM, NB / BN);   // 16 x 8 = 128 blocks
    trop_mm_kernel<<<grid, THREADS>>>(x, M, (float*)d_out);
}